// round 16
// baseline (speedup 1.0000x reference)
#include <cuda_runtime.h>
#include <cstddef>

// Problem constants (fixed by setup_inputs)
#define BB 2
#define DD 48
#define HH 320
#define WW 640
#define RR 2
#define KK 5
#define K2 25
#define HW (HH * WW)

// Tiling: 16x32 output tile, 256 threads, 2 vertical pixels per thread.
// DC=12 disparities per block (4 chunks) -> 3200 blocks: wave tail 1.8% vs 11%.
// chunk is the fastest grid dim so a tile's 4 chunk-blocks share weight lines
// in L2 within the same wave.
#define TH 16
#define TW 32
#define DC 12
#define NCHUNK (DD / DC)   // 4
#define PH (TH + 2 * RR)   // 20
#define PW (TW + 2 * RR)   // 36
#define PD (DC + 2)        // 14 planes used
#define PDP 20             // plane stride (80B -> conflict-free LDS.128)
#define NT 256
#define SMEM_BYTES (PH * PW * PDP * 4)   // 57600
#define NTAPS (KK * (KK + 1))            // 30 flattened (i,j) taps
#define PSTAGES 4                        // weight pipeline depth (3 ahead)

// Intermediate buffer for pass-1 result (allocation-free scratch)
__device__ float g_y[(size_t)BB * DD * HH * WW];

__device__ __forceinline__ unsigned long long pk2(float lo, float hi) {
    unsigned long long r;
    asm("mov.b64 %0, {%1, %2};" : "=l"(r) : "f"(lo), "f"(hi));
    return r;
}
__device__ __forceinline__ void ffma2(unsigned long long &acc,
                                      unsigned long long a,
                                      unsigned long long b) {
    asm("fma.rn.f32x2 %0, %1, %2, %0;" : "+l"(acc) : "l"(a), "l"(b));
}

union Acc { unsigned long long u; float2 f; };
union Q4 { float4 f; unsigned long long u[2]; float s[4]; };
union Q2 { float2 f; unsigned long long u; float s[2]; };

// Load one flattened tap's 6 weights (3 for pixel0 row, 3 for pixel1 row).
// fi is compile-time under full unroll; invalid groups load nothing (stay 0).
__device__ __forceinline__ void load_tap(int fi, const float* wb0,
                                         const float* wb1, float* P)
{
    const int i = fi / KK;
    const int j = fi - i * KK;
    P[0] = 0.f; P[1] = 0.f; P[2] = 0.f; P[3] = 0.f; P[4] = 0.f; P[5] = 0.f;
    if (i < KK) {            // pixel0 tap (i, j)
        P[0] = __ldg(wb0 + (size_t)(0 * K2 + i * KK + j) * HW);
        P[1] = __ldg(wb0 + (size_t)(1 * K2 + i * KK + j) * HW);
        P[2] = __ldg(wb0 + (size_t)(2 * K2 + i * KK + j) * HW);
    }
    if (i >= 1) {            // pixel1 tap (i-1, j)
        P[3] = __ldg(wb1 + (size_t)(0 * K2 + (i - 1) * KK + j) * HW);
        P[4] = __ldg(wb1 + (size_t)(1 * K2 + (i - 1) * KK + j) * HW);
        P[5] = __ldg(wb1 + (size_t)(2 * K2 + (i - 1) * KK + j) * HW);
    }
}

// One fill position: unconditional clamped-disparity loads + zero fixups.
// Only chunk 0 (gd=-1) and the last chunk (gd=DD) have one invalid plane.
__device__ __forceinline__ void fill_pos(int pos, int h0, int w0p, int b, int d0,
                                         const float* __restrict__ xin, float* xs)
{
    const int row = pos / PW;
    const int col = pos - row * PW;
    const int hh = h0 + row - RR;
    const int ww = w0p + col - RR;
    const bool sok = ((unsigned)hh < HH) & ((unsigned)ww < WW);

    float buf[PDP];
    if (sok) {
        const float* src = xin + ((size_t)b * DD * HH + hh) * (size_t)WW + ww;
        const int gdbase = d0 - 1;
        #pragma unroll
        for (int p = 0; p < PD; ++p) {
            int gd = gdbase + p;
            gd = (gd < 0) ? 0 : ((gd > DD - 1) ? DD - 1 : gd);
            buf[p] = __ldg(src + (size_t)gd * HW);
        }
        if (d0 == 0) buf[0] = 0.0f;
        if (d0 + DC == DD) buf[PD - 1] = 0.0f;
    } else {
        #pragma unroll
        for (int p = 0; p < PD; ++p) buf[p] = 0.0f;
    }
    #pragma unroll
    for (int p = PD; p < PDP; ++p) buf[p] = 0.0f;

    float4* dst = (float4*)&xs[pos * PDP];
    #pragma unroll
    for (int q = 0; q < PDP / 4; ++q)
        dst[q] = make_float4(buf[4*q], buf[4*q+1], buf[4*q+2], buf[4*q+3]);
}

__global__ void __launch_bounds__(NT, 2)
lga_kernel(const float* __restrict__ xin,
           const float* __restrict__ wts,
           float* __restrict__ xout)
{
    extern __shared__ float xs[];   // [PH][PW][PDP]

    const int t  = threadIdx.x;
    const int tx = t & 31;       // W within tile
    const int ty = t >> 5;       // 0..7 -> output rows 2ty, 2ty+1

    const int bx    = blockIdx.x;
    const int chunk = bx & (NCHUNK - 1);     // fastest dim: tile's chunks adjacent
    const int w0p   = (bx / NCHUNK) * TW;
    const int h0    = blockIdx.y * TH;
    const int b     = blockIdx.z;
    const int d0    = chunk * DC;

    const int gh0 = h0 + 2 * ty;
    const int gw  = w0p + tx;

    // weight base: wts[b, c, gh, gw], channel stride = HW
    const float* wb0 = wts + ((size_t)b * (3 * K2)) * HW + (size_t)gh0 * WW + gw;
    const float* wb1 = wb0 + WW;   // row gh0+1

    // thread's column base in the slab; per-tap offset is a compile-time const
    float* const xsb = &xs[(2 * ty * PW + tx) * PDP];

    // ---- prime the 4-stage weight pipeline BEFORE the grid sync + fill ----
    // (weights are original inputs -> independent of the previous pass)
    float P[PSTAGES][6];
    load_tap(0, wb0, wb1, P[0]);
    load_tap(1, wb0, wb1, P[1]);
    load_tap(2, wb0, wb1, P[2]);

    // PDL: wait for the producer pass before reading xin (y for pass 2).
    cudaGridDependencySynchronize();

    // ---- fill shared slab: 2 unconditional strides + 1 guarded ----
    fill_pos(t,           h0, w0p, b, d0, xin, xs);
    fill_pos(t + NT,      h0, w0p, b, d0, xin, xs);
    if (t + 2 * NT < PH * PW)
        fill_pos(t + 2 * NT, h0, w0p, b, d0, xin, xs);
    __syncthreads();

    // ---- two vertically adjacent pixels per thread ----
    Acc acc0[DC / 2], acc1[DC / 2];
    #pragma unroll
    for (int k = 0; k < DC / 2; ++k) { acc0[k].u = 0ull; acc1[k].u = 0ull; }

    // pixel0 tap (i,j) -> slab row 2ty+i ; pixel1 tap (i,j) -> row 2ty+1+i.
    // W1/W2 groups use aligned packed pairs (FFMA2); the W0 group (odd
    // alignment) uses scalar FFMAs into the pair halves -> no pack movs.
    #pragma unroll
    for (int fi = 0; fi < NTAPS; ++fi) {
        const int i = fi / KK;
        const int j = fi - i * KK;

        if (fi + 3 < NTAPS)
            load_tap(fi + 3, wb0, wb1, P[(fi + 3) % PSTAGES]);

        const float* Pc = P[fi % PSTAGES];
        unsigned long long W1a = 0, W2a = 0, W1b = 0, W2b = 0;
        float w0a = 0.f, w0b = 0.f;
        if (i < KK) { w0a = Pc[0]; W1a = pk2(Pc[1], Pc[1]); W2a = pk2(Pc[2], Pc[2]); }
        if (i >= 1) { w0b = Pc[3]; W1b = pk2(Pc[4], Pc[4]); W2b = pk2(Pc[5], Pc[5]); }

        // disparity column at compile-time slab offset; sliding 2-quad window
        const float* cb = xsb + (i * PW + j) * PDP;

        Q4 qa, qb; Q2 qt;
        qa.f = *(const float4*)(cb + 0);

        #pragma unroll
        for (int tq = 0; tq < DC / 4; ++tq) {
            // load next quad (or tail pair) of the column
            if (tq < DC / 4 - 1) {
                qb.f = *(const float4*)(cb + 4 * (tq + 1));
            } else {
                qt.f = *(const float2*)(cb + DC);   // c[DC], c[DC+1]
                qb.u[0] = qt.u;
            }
            // pair k = 2*tq : E=qa.u[0]; W0 scalars qa.s[1], qa.s[2]; E'=qa.u[1]
            {
                const int k = 2 * tq;
                if (i < KK) {
                    ffma2(acc0[k].u, W1a, qa.u[0]);
                    acc0[k].f.x = fmaf(w0a, qa.s[1], acc0[k].f.x);
                    acc0[k].f.y = fmaf(w0a, qa.s[2], acc0[k].f.y);
                    ffma2(acc0[k].u, W2a, qa.u[1]);
                }
                if (i >= 1) {
                    ffma2(acc1[k].u, W1b, qa.u[0]);
                    acc1[k].f.x = fmaf(w0b, qa.s[1], acc1[k].f.x);
                    acc1[k].f.y = fmaf(w0b, qa.s[2], acc1[k].f.y);
                    ffma2(acc1[k].u, W2b, qa.u[1]);
                }
            }
            // pair k = 2*tq+1 : W0 scalars use qa.s[3], qb.s[0]; E'=qb.u[0]
            {
                const int k = 2 * tq + 1;
                if (i < KK) {
                    ffma2(acc0[k].u, W1a, qa.u[1]);
                    acc0[k].f.x = fmaf(w0a, qa.s[3], acc0[k].f.x);
                    acc0[k].f.y = fmaf(w0a, qb.s[0], acc0[k].f.y);
                    ffma2(acc0[k].u, W2a, qb.u[0]);
                }
                if (i >= 1) {
                    ffma2(acc1[k].u, W1b, qa.u[1]);
                    acc1[k].f.x = fmaf(w0b, qa.s[3], acc1[k].f.x);
                    acc1[k].f.y = fmaf(w0b, qb.s[0], acc1[k].f.y);
                    ffma2(acc1[k].u, W2b, qb.u[0]);
                }
            }
            if (tq < DC / 4 - 1) {
                qa.f = qb.f;
            }
        }
    }

    // ---- write out (coalesced along tx) ----
    float* outp0 = xout + (((size_t)b * DD + d0) * HH + gh0) * (size_t)WW + gw;
    float* outp1 = outp0 + WW;
    #pragma unroll
    for (int k = 0; k < DC / 2; ++k) {
        outp0[(size_t)(2 * k) * HW]     = acc0[k].f.x;
        outp0[(size_t)(2 * k + 1) * HW] = acc0[k].f.y;
        outp1[(size_t)(2 * k) * HW]     = acc1[k].f.x;
        outp1[(size_t)(2 * k + 1) * HW] = acc1[k].f.y;
    }

    // PDL: allow the dependent pass to launch.
    cudaTriggerProgrammaticLaunchCompletion();
}

static void launch_pass(const float* xin, const float* w, float* xout, bool pdl)
{
    cudaLaunchConfig_t cfg = {};
    cfg.gridDim  = dim3((WW / TW) * NCHUNK, HH / TH, BB);   // 80 x 20 x 2 = 3200
    cfg.blockDim = dim3(NT, 1, 1);
    cfg.dynamicSmemBytes = SMEM_BYTES;
    cfg.stream = 0;
    cudaLaunchAttribute attr[1];
    attr[0].id = cudaLaunchAttributeProgrammaticStreamSerialization;
    attr[0].val.programmaticStreamSerializationAllowed = 1;
    cfg.attrs = pdl ? attr : nullptr;
    cfg.numAttrs = pdl ? 1 : 0;
    cudaLaunchKernelEx(&cfg, lga_kernel, xin, w, xout);
}

extern "C" void kernel_launch(void* const* d_in, const int* in_sizes, int n_in,
                              void* d_out, int out_size)
{
    const float* x = (const float*)d_in[0];   // [B, D, H, W]
    const float* w = (const float*)d_in[1];   // [B, 75, H, W]
    float* out = (float*)d_out;

    float* ybuf = nullptr;
    cudaGetSymbolAddress((void**)&ybuf, g_y);

    cudaFuncSetAttribute(lga_kernel,
                         cudaFuncAttributeMaxDynamicSharedMemorySize, SMEM_BYTES);

    launch_pass(x,    w, ybuf, false);   // pass 1
    launch_pass(ybuf, w, out,  true);    // pass 2 (PDL overlap with pass-1 tail)
}

// round 17
// speedup vs baseline: 1.1310x; 1.1310x over previous
#include <cuda_runtime.h>
#include <cstddef>

// Problem constants (fixed by setup_inputs)
#define BB 2
#define DD 48
#define HH 320
#define WW 640
#define RR 2
#define KK 5
#define K2 25
#define HW (HH * WW)

// Tiling: 16x32 output tile, 256 threads, 2 vertical pixels per thread.
// One D-chunk (24 disparities) per block; chunk is the fastest grid dim so
// the two chunks of a tile share weight lines in L2 within the same wave.
#define TH 16
#define TW 32
#define DC 24
#define NCHUNK (DD / DC)   // 2
#define PH (TH + 2 * RR)   // 20
#define PW (TW + 2 * RR)   // 36
#define PD (DC + 2)        // 26 planes used
#define PDP 28             // plane stride (112B -> conflict-free LDS.128)
#define NT 256
#define SMEM_BYTES (PH * PW * PDP * 4)   // 80640
#define NTAPS (KK * (KK + 1))            // 30 flattened (i,j) taps
#define PSTAGES 4                        // weight pipeline depth (3 ahead)

// Intermediate buffer for pass-1 result (allocation-free scratch)
__device__ float g_y[(size_t)BB * DD * HH * WW];

__device__ __forceinline__ unsigned long long pk2(float lo, float hi) {
    unsigned long long r;
    asm("mov.b64 %0, {%1, %2};" : "=l"(r) : "f"(lo), "f"(hi));
    return r;
}
__device__ __forceinline__ void ffma2(unsigned long long &acc,
                                      unsigned long long a,
                                      unsigned long long b) {
    asm("fma.rn.f32x2 %0, %1, %2, %0;" : "+l"(acc) : "l"(a), "l"(b));
}

union Acc { unsigned long long u; float2 f; };
union Q4 { float4 f; unsigned long long u[2]; float s[4]; };
union Q2 { float2 f; unsigned long long u; float s[2]; };

// Load one flattened tap's 6 weights (3 for pixel0 row, 3 for pixel1 row).
// fi is compile-time under full unroll; invalid groups load nothing (stay 0).
__device__ __forceinline__ void load_tap(int fi, const float* wb0,
                                         const float* wb1, float* P)
{
    const int i = fi / KK;
    const int j = fi - i * KK;
    P[0] = 0.f; P[1] = 0.f; P[2] = 0.f; P[3] = 0.f; P[4] = 0.f; P[5] = 0.f;
    if (i < KK) {            // pixel0 tap (i, j)
        P[0] = __ldg(wb0 + (size_t)(0 * K2 + i * KK + j) * HW);
        P[1] = __ldg(wb0 + (size_t)(1 * K2 + i * KK + j) * HW);
        P[2] = __ldg(wb0 + (size_t)(2 * K2 + i * KK + j) * HW);
    }
    if (i >= 1) {            // pixel1 tap (i-1, j)
        P[3] = __ldg(wb1 + (size_t)(0 * K2 + (i - 1) * KK + j) * HW);
        P[4] = __ldg(wb1 + (size_t)(1 * K2 + (i - 1) * KK + j) * HW);
        P[5] = __ldg(wb1 + (size_t)(2 * K2 + (i - 1) * KK + j) * HW);
    }
}

// One fill position: unconditional clamped-disparity loads + single zero fixup.
// For chunk 0 only plane 0 (gd=-1) is invalid; for chunk 1 only plane 25 (gd=48).
__device__ __forceinline__ void fill_pos(int pos, int h0, int w0p, int b, int d0,
                                         const float* __restrict__ xin, float* xs)
{
    const int row = pos / PW;
    const int col = pos - row * PW;
    const int hh = h0 + row - RR;
    const int ww = w0p + col - RR;
    const bool sok = ((unsigned)hh < HH) & ((unsigned)ww < WW);

    float buf[PDP];
    if (sok) {
        const float* src = xin + ((size_t)b * DD * HH + hh) * (size_t)WW + ww;
        // clamp gd into [0, DD-1]; exactly one plane is out-of-range per chunk
        const int gdbase = d0 - 1;                    // -1 or 23
        #pragma unroll
        for (int p = 0; p < PD; ++p) {
            int gd = gdbase + p;
            gd = (gd < 0) ? 0 : ((gd > DD - 1) ? DD - 1 : gd);
            buf[p] = __ldg(src + (size_t)gd * HW);
        }
        if (d0 == 0) buf[0] = 0.0f; else buf[PD - 1] = 0.0f;
    } else {
        #pragma unroll
        for (int p = 0; p < PD; ++p) buf[p] = 0.0f;
    }
    buf[PD] = 0.0f; buf[PD + 1] = 0.0f;

    float4* dst = (float4*)&xs[pos * PDP];
    #pragma unroll
    for (int q = 0; q < PDP / 4; ++q)
        dst[q] = make_float4(buf[4*q], buf[4*q+1], buf[4*q+2], buf[4*q+3]);
}

__global__ void __launch_bounds__(NT, 2)
lga_kernel(const float* __restrict__ xin,
           const float* __restrict__ wts,
           float* __restrict__ xout)
{
    extern __shared__ float xs[];   // [PH][PW][PDP]

    const int t  = threadIdx.x;
    const int tx = t & 31;       // W within tile
    const int ty = t >> 5;       // 0..7 -> output rows 2ty, 2ty+1

    const int bx    = blockIdx.x;
    const int chunk = bx & 1;            // fastest dim: chunks of a tile adjacent
    const int w0p   = (bx >> 1) * TW;
    const int h0    = blockIdx.y * TH;
    const int b     = blockIdx.z;
    const int d0    = chunk * DC;

    const int gh0 = h0 + 2 * ty;
    const int gw  = w0p + tx;

    // weight base: wts[b, c, gh, gw], channel stride = HW
    const float* wb0 = wts + ((size_t)b * (3 * K2)) * HW + (size_t)gh0 * WW + gw;
    const float* wb1 = wb0 + WW;   // row gh0+1

    // thread's column base in the slab; per-tap offset is a compile-time const
    float* const xsb = &xs[(2 * ty * PW + tx) * PDP];

    // ---- prime the 4-stage weight pipeline BEFORE the grid sync + fill ----
    // (weights are original inputs -> independent of the previous pass, so
    // pass-2 blocks launched early via PDL do this during pass-1's tail)
    float P[PSTAGES][6];
    load_tap(0, wb0, wb1, P[0]);
    load_tap(1, wb0, wb1, P[1]);
    load_tap(2, wb0, wb1, P[2]);

    // PDL: wait for the producer pass before reading xin (y for pass 2).
    cudaGridDependencySynchronize();

    // ---- fill shared slab: 2 unconditional strides + 1 guarded ----
    fill_pos(t,           h0, w0p, b, d0, xin, xs);
    fill_pos(t + NT,      h0, w0p, b, d0, xin, xs);
    if (t + 2 * NT < PH * PW)
        fill_pos(t + 2 * NT, h0, w0p, b, d0, xin, xs);
    __syncthreads();

    // ---- two vertically adjacent pixels per thread ----
    Acc acc0[DC / 2], acc1[DC / 2];
    #pragma unroll
    for (int k = 0; k < DC / 2; ++k) { acc0[k].u = 0ull; acc1[k].u = 0ull; }

    // pixel0 tap (i,j) -> slab row 2ty+i ; pixel1 tap (i,j) -> row 2ty+1+i.
    // W1/W2 groups use aligned packed pairs (FFMA2); the W0 group (odd
    // alignment) uses scalar FFMAs into the pair halves -> no pack movs.
    #pragma unroll
    for (int fi = 0; fi < NTAPS; ++fi) {
        const int i = fi / KK;
        const int j = fi - i * KK;

        if (fi + 3 < NTAPS)
            load_tap(fi + 3, wb0, wb1, P[(fi + 3) % PSTAGES]);

        const float* Pc = P[fi % PSTAGES];
        unsigned long long W1a = 0, W2a = 0, W1b = 0, W2b = 0;
        float w0a = 0.f, w0b = 0.f;
        if (i < KK) { w0a = Pc[0]; W1a = pk2(Pc[1], Pc[1]); W2a = pk2(Pc[2], Pc[2]); }
        if (i >= 1) { w0b = Pc[3]; W1b = pk2(Pc[4], Pc[4]); W2b = pk2(Pc[5], Pc[5]); }

        // disparity column at compile-time slab offset; sliding 2-quad window
        const float* cb = xsb + (i * PW + j) * PDP;

        Q4 qa, qb; Q2 qt;
        qa.f = *(const float4*)(cb + 0);

        #pragma unroll
        for (int tq = 0; tq < DC / 4; ++tq) {
            // load next quad (or tail pair) of the column
            if (tq < DC / 4 - 1) {
                qb.f = *(const float4*)(cb + 4 * (tq + 1));
            } else {
                qt.f = *(const float2*)(cb + DC);   // c[DC], c[DC+1]
                qb.u[0] = qt.u;
            }
            // pair k = 2*tq : E=qa.u[0]; W0 scalars qa.s[1], qa.s[2]; E'=qa.u[1]
            {
                const int k = 2 * tq;
                if (i < KK) {
                    ffma2(acc0[k].u, W1a, qa.u[0]);
                    acc0[k].f.x = fmaf(w0a, qa.s[1], acc0[k].f.x);
                    acc0[k].f.y = fmaf(w0a, qa.s[2], acc0[k].f.y);
                    ffma2(acc0[k].u, W2a, qa.u[1]);
                }
                if (i >= 1) {
                    ffma2(acc1[k].u, W1b, qa.u[0]);
                    acc1[k].f.x = fmaf(w0b, qa.s[1], acc1[k].f.x);
                    acc1[k].f.y = fmaf(w0b, qa.s[2], acc1[k].f.y);
                    ffma2(acc1[k].u, W2b, qa.u[1]);
                }
            }
            // pair k = 2*tq+1 : W0 scalars use qa.s[3], qb.s[0]; E'=qb.u[0]
            {
                const int k = 2 * tq + 1;
                if (i < KK) {
                    ffma2(acc0[k].u, W1a, qa.u[1]);
                    acc0[k].f.x = fmaf(w0a, qa.s[3], acc0[k].f.x);
                    acc0[k].f.y = fmaf(w0a, qb.s[0], acc0[k].f.y);
                    ffma2(acc0[k].u, W2a, qb.u[0]);
                }
                if (i >= 1) {
                    ffma2(acc1[k].u, W1b, qa.u[1]);
                    acc1[k].f.x = fmaf(w0b, qa.s[3], acc1[k].f.x);
                    acc1[k].f.y = fmaf(w0b, qb.s[0], acc1[k].f.y);
                    ffma2(acc1[k].u, W2b, qb.u[0]);
                }
            }
            if (tq < DC / 4 - 1) {
                qa.f = qb.f;
            }
        }
    }

    // ---- write out (coalesced along tx) ----
    float* outp0 = xout + (((size_t)b * DD + d0) * HH + gh0) * (size_t)WW + gw;
    float* outp1 = outp0 + WW;
    #pragma unroll
    for (int k = 0; k < DC / 2; ++k) {
        outp0[(size_t)(2 * k) * HW]     = acc0[k].f.x;
        outp0[(size_t)(2 * k + 1) * HW] = acc0[k].f.y;
        outp1[(size_t)(2 * k) * HW]     = acc1[k].f.x;
        outp1[(size_t)(2 * k + 1) * HW] = acc1[k].f.y;
    }

    // PDL: allow the dependent pass to launch into our tail.
    cudaTriggerProgrammaticLaunchCompletion();
}

static void launch_pass(const float* xin, const float* w, float* xout, bool pdl)
{
    cudaLaunchConfig_t cfg = {};
    cfg.gridDim  = dim3((WW / TW) * NCHUNK, HH / TH, BB);   // 40 x 20 x 2 = 1600
    cfg.blockDim = dim3(NT, 1, 1);
    cfg.dynamicSmemBytes = SMEM_BYTES;
    cfg.stream = 0;
    cudaLaunchAttribute attr[1];
    attr[0].id = cudaLaunchAttributeProgrammaticStreamSerialization;
    attr[0].val.programmaticStreamSerializationAllowed = 1;
    cfg.attrs = pdl ? attr : nullptr;
    cfg.numAttrs = pdl ? 1 : 0;
    cudaLaunchKernelEx(&cfg, lga_kernel, xin, w, xout);
}

extern "C" void kernel_launch(void* const* d_in, const int* in_sizes, int n_in,
                              void* d_out, int out_size)
{
    const float* x = (const float*)d_in[0];   // [B, D, H, W]
    const float* w = (const float*)d_in[1];   // [B, 75, H, W]
    float* out = (float*)d_out;

    float* ybuf = nullptr;
    cudaGetSymbolAddress((void**)&ybuf, g_y);

    cudaFuncSetAttribute(lga_kernel,
                         cudaFuncAttributeMaxDynamicSharedMemorySize, SMEM_BYTES);

    launch_pass(x,    w, ybuf, false);   // pass 1
    launch_pass(ybuf, w, out,  true);    // pass 2 (PDL overlap with pass-1 tail)
}